// round 6
// baseline (speedup 1.0000x reference)
#include <cuda_runtime.h>
#include <cuda_bf16.h>

// FPN RoIAlign: 5 levels (p2..p6, strides 4..64 -> hw 256..16), NHWC fp32, C=256.
// B=2, R=512, OUT=7x7, sampling_ratio=2 (2x2 subsamples per bin).
// One CTA per box; 256 threads = 4 groups x 64 threads.
// Each group handles bins {g, g+4, ...}; within a group each thread owns 4
// consecutive channels (float4), so every corner gather is one fully
// coalesced 1KB LDG.128 wavefront per group. Corner loads are batched in
// two groups of 8 (MLP=8 per batch, ~60 live regs -> 3-4 CTAs/SM).

#define RR 512
#define CC 256
#define NSAMP 196   // 7*7*2*2

__global__ __launch_bounds__(256) void roi_align_fpn_kernel(
    const float* __restrict__ p2, const float* __restrict__ p3,
    const float* __restrict__ p4, const float* __restrict__ p5,
    const float* __restrict__ p6, const float* __restrict__ prop,
    float* __restrict__ out)
{
    const int r    = blockIdx.x;
    const int bimg = blockIdx.y;
    const int tid  = threadIdx.x;

    // Box in image coords
    const float4 box = reinterpret_cast<const float4*>(prop)[bimg * RR + r];

    // Level assignment: lvl = clip(floor(4 + log2(sqrt(w*h)/224)), 2, 6)
    float bw = fmaxf(box.z - box.x, 1.0f);
    float bh = fmaxf(box.w - box.y, 1.0f);
    float lvlf = floorf(4.0f + log2f(sqrtf(bw * bh) * (1.0f / 224.0f)));
    int lvl = (int)fminf(fmaxf(lvlf, 2.0f), 6.0f);

    // hw = 1024 / stride, stride = 2^lvl
    const float* __restrict__ f;
    int H;
    switch (lvl) {
        case 2:  f = p2; H = 256; break;   // stride 4
        case 3:  f = p3; H = 128; break;   // stride 8
        case 4:  f = p4; H = 64;  break;   // stride 16
        case 5:  f = p5; H = 32;  break;   // stride 32
        default: f = p6; H = 16;  break;   // stride 64
    }
    const float scale = 1.0f / (float)(1 << lvl);

    // Scaled box on this level's feature map
    const float x1 = box.x * scale;
    const float y1 = box.y * scale;
    const float x2 = box.z * scale;
    const float y2 = box.w * scale;
    const float roi_w = fmaxf(x2 - x1, 1.0f);
    const float roi_h = fmaxf(y2 - y1, 1.0f);
    const float bin_w = roi_w * (1.0f / 7.0f);
    const float bin_h = roi_h * (1.0f / 7.0f);

    // Precomputed sample geometry: float4 offsets (in float4 units, incl.
    // batch base) + bilinear weights, one entry per subsample.
    __shared__ int   s_off[4][NSAMP];
    __shared__ float s_wt [4][NSAMP];

    if (tid < NSAMP) {
        const int i  = tid;
        const int sx = i & 1;
        const int sy = (i >> 1) & 1;
        const int bin = i >> 2;
        const int ow = bin % 7;
        const int oh = bin / 7;

        const float fh = (float)H;
        float Y = y1 + ((float)oh + ((float)sy + 0.5f) * 0.5f) * bin_h;
        float X = x1 + ((float)ow + ((float)sx + 0.5f) * 0.5f) * bin_w;

        bool valid = (Y >= -1.0f) && (Y <= fh) && (X >= -1.0f) && (X <= fh);

        float y = fminf(fmaxf(Y, 0.0f), fh - 1.0f);
        float x = fminf(fmaxf(X, 0.0f), fh - 1.0f);
        float y0 = floorf(y);
        float x0 = floorf(x);
        int y0i = (int)y0;
        int x0i = (int)x0;
        int y1i = min(y0i + 1, H - 1);
        int x1i = min(x0i + 1, H - 1);
        float ly = y - y0, lx = x - x0;
        float hy = 1.0f - ly, hx = 1.0f - lx;
        float v = valid ? 1.0f : 0.0f;

        // offsets in units of float4 (CC/4 = 64 float4 per pixel)
        const int base = bimg * H * H * (CC / 4);
        s_off[0][i] = base + (y0i * H + x0i) * (CC / 4);
        s_off[1][i] = base + (y0i * H + x1i) * (CC / 4);
        s_off[2][i] = base + (y1i * H + x0i) * (CC / 4);
        s_off[3][i] = base + (y1i * H + x1i) * (CC / 4);
        s_wt[0][i] = hy * hx * v;
        s_wt[1][i] = hy * lx * v;
        s_wt[2][i] = ly * hx * v;
        s_wt[3][i] = ly * lx * v;
    }
    __syncthreads();

    const int group = tid >> 6;       // 0..3: bin subset
    const int c4    = tid & 63;       // float4 channel index (0..63)

    const float4* __restrict__ f4 = reinterpret_cast<const float4*>(f);
    float4* __restrict__ o4 = reinterpret_cast<float4*>(out)
                            + ((size_t)(bimg * RR + r) * 49) * (CC / 4) + c4;

    for (int bin = group; bin < 49; bin += 4) {
        float4 acc = make_float4(0.f, 0.f, 0.f, 0.f);
        // Two half-bin batches of 8 loads each (subsamples {0,1} then {2,3}).
        #pragma unroll
        for (int half = 0; half < 2; ++half) {
            float4 v[8];
            float  w[8];
            #pragma unroll
            for (int s = 0; s < 2; ++s) {
                const int i = bin * 4 + half * 2 + s;
                #pragma unroll
                for (int k = 0; k < 4; ++k) {
                    w[s * 4 + k] = s_wt[k][i];
                    v[s * 4 + k] = __ldg(f4 + s_off[k][i] + c4);
                }
            }
            #pragma unroll
            for (int j = 0; j < 8; ++j) {
                acc.x += w[j] * v[j].x;
                acc.y += w[j] * v[j].y;
                acc.z += w[j] * v[j].z;
                acc.w += w[j] * v[j].w;
            }
        }
        acc.x *= 0.25f; acc.y *= 0.25f; acc.z *= 0.25f; acc.w *= 0.25f;
        o4[(size_t)bin * (CC / 4)] = acc;
    }
}

extern "C" void kernel_launch(void* const* d_in, const int* in_sizes, int n_in,
                              void* d_out, int out_size) {
    // Identify inputs by element count (all six are distinct).
    // hw = 1024/stride: p2=256, p3=128, p4=64, p5=32, p6=16; C=256, B=2.
    const float *p2 = nullptr, *p3 = nullptr, *p4 = nullptr,
                *p5 = nullptr, *p6 = nullptr, *prop = nullptr;
    for (int i = 0; i < n_in; ++i) {
        switch (in_sizes[i]) {
            case 33554432:  p2   = (const float*)d_in[i]; break; // 2*256*256*256
            case 8388608:   p3   = (const float*)d_in[i]; break; // 2*128*128*256
            case 2097152:   p4   = (const float*)d_in[i]; break; // 2*64*64*256
            case 524288:    p5   = (const float*)d_in[i]; break; // 2*32*32*256
            case 131072:    p6   = (const float*)d_in[i]; break; // 2*16*16*256
            case 4096:      prop = (const float*)d_in[i]; break; // 2*512*4
        }
    }
    dim3 grid(RR, 2);
    roi_align_fpn_kernel<<<grid, 256>>>(p2, p3, p4, p5, p6, prop, (float*)d_out);
}

// round 8
// speedup vs baseline: 1.0993x; 1.0993x over previous
#include <cuda_runtime.h>
#include <cuda_bf16.h>

// FPN RoIAlign: 5 levels (p2..p6, hw 256..16), NHWC fp32, C=256.
// B=2, R=512, OUT=7x7, sr=2. One CTA per box; 256 threads = 4 groups x 64.
// Group g handles bins {g, g+4, ...}; each thread owns 4 consecutive channels
// (float4) -> every corner gather is a fully coalesced 1KB wavefront per group.
// Geometry packed as int4 offsets + float4 weights per subsample (LDS.128 x2).

#define RR 512
#define CC 256
#define NSAMP 196   // 7*7*2*2

struct Geo {
    int4   off;   // byte offsets of the 4 bilinear corners (incl. batch base)
    float4 wt;    // matching bilinear weights (0 if sample invalid)
};

__global__ __launch_bounds__(256, 5) void roi_align_fpn_kernel(
    const float* __restrict__ p2, const float* __restrict__ p3,
    const float* __restrict__ p4, const float* __restrict__ p5,
    const float* __restrict__ p6, const float* __restrict__ prop,
    float* __restrict__ out)
{
    const int r    = blockIdx.x;
    const int bimg = blockIdx.y;
    const int tid  = threadIdx.x;

    // Box in image coords
    const float4 box = reinterpret_cast<const float4*>(prop)[bimg * RR + r];

    // Level assignment: lvl = clip(floor(4 + log2(sqrt(w*h)/224)), 2, 6)
    float bw = fmaxf(box.z - box.x, 1.0f);
    float bh = fmaxf(box.w - box.y, 1.0f);
    float lvlf = floorf(4.0f + log2f(sqrtf(bw * bh) * (1.0f / 224.0f)));
    int lvl = (int)fminf(fmaxf(lvlf, 2.0f), 6.0f);

    // hw = 1024 / stride, stride = 2^lvl
    const float* __restrict__ f;
    int H;
    switch (lvl) {
        case 2:  f = p2; H = 256; break;
        case 3:  f = p3; H = 128; break;
        case 4:  f = p4; H = 64;  break;
        case 5:  f = p5; H = 32;  break;
        default: f = p6; H = 16;  break;
    }
    const float scale = 1.0f / (float)(1 << lvl);

    const float x1 = box.x * scale;
    const float y1 = box.y * scale;
    const float x2 = box.z * scale;
    const float y2 = box.w * scale;
    const float roi_w = fmaxf(x2 - x1, 1.0f);
    const float roi_h = fmaxf(y2 - y1, 1.0f);
    const float bin_w = roi_w * (1.0f / 7.0f);
    const float bin_h = roi_h * (1.0f / 7.0f);

    __shared__ Geo s_geo[NSAMP];

    if (tid < NSAMP) {
        const int i  = tid;
        const int sx = i & 1;
        const int sy = (i >> 1) & 1;
        const int bin = i >> 2;
        const int ow = bin % 7;
        const int oh = bin / 7;

        const float fh = (float)H;
        float Y = y1 + ((float)oh + ((float)sy + 0.5f) * 0.5f) * bin_h;
        float X = x1 + ((float)ow + ((float)sx + 0.5f) * 0.5f) * bin_w;

        bool valid = (Y >= -1.0f) && (Y <= fh) && (X >= -1.0f) && (X <= fh);

        float y = fminf(fmaxf(Y, 0.0f), fh - 1.0f);
        float x = fminf(fmaxf(X, 0.0f), fh - 1.0f);
        float y0 = floorf(y);
        float x0 = floorf(x);
        int y0i = (int)y0;
        int x0i = (int)x0;
        int y1i = min(y0i + 1, H - 1);
        int x1i = min(x0i + 1, H - 1);
        float ly = y - y0, lx = x - x0;
        float hy = 1.0f - ly, hx = 1.0f - lx;
        float v = valid ? 1.0f : 0.0f;

        // byte offsets: pixel row = 256 floats = 1024 bytes
        const int base = bimg * H * H * 1024;
        Geo g;
        g.off.x = base + (y0i * H + x0i) * 1024;
        g.off.y = base + (y0i * H + x1i) * 1024;
        g.off.z = base + (y1i * H + x0i) * 1024;
        g.off.w = base + (y1i * H + x1i) * 1024;
        g.wt.x = hy * hx * v;
        g.wt.y = hy * lx * v;
        g.wt.z = ly * hx * v;
        g.wt.w = ly * lx * v;
        s_geo[i] = g;
    }
    __syncthreads();

    const int group = tid >> 6;       // 0..3: bin subset
    const int c4    = tid & 63;       // float4 channel index (0..63)

    // per-thread channel base in bytes
    const char* __restrict__ fb = reinterpret_cast<const char*>(f) + c4 * 16;
    float4* __restrict__ o4 = reinterpret_cast<float4*>(out)
                            + ((size_t)(bimg * RR + r) * 49) * 64 + c4;

    for (int bin = group; bin < 49; bin += 4) {
        float4 acc = make_float4(0.f, 0.f, 0.f, 0.f);
        // Two half-bin batches: 2 subsamples (8 corner loads, MLP=8) each.
        #pragma unroll
        for (int half = 0; half < 2; ++half) {
            const Geo g0 = s_geo[bin * 4 + half * 2 + 0];
            const Geo g1 = s_geo[bin * 4 + half * 2 + 1];
            float4 v0 = __ldg((const float4*)(fb + g0.off.x));
            float4 v1 = __ldg((const float4*)(fb + g0.off.y));
            float4 v2 = __ldg((const float4*)(fb + g0.off.z));
            float4 v3 = __ldg((const float4*)(fb + g0.off.w));
            float4 v4 = __ldg((const float4*)(fb + g1.off.x));
            float4 v5 = __ldg((const float4*)(fb + g1.off.y));
            float4 v6 = __ldg((const float4*)(fb + g1.off.z));
            float4 v7 = __ldg((const float4*)(fb + g1.off.w));
            acc.x += g0.wt.x * v0.x; acc.y += g0.wt.x * v0.y; acc.z += g0.wt.x * v0.z; acc.w += g0.wt.x * v0.w;
            acc.x += g0.wt.y * v1.x; acc.y += g0.wt.y * v1.y; acc.z += g0.wt.y * v1.z; acc.w += g0.wt.y * v1.w;
            acc.x += g0.wt.z * v2.x; acc.y += g0.wt.z * v2.y; acc.z += g0.wt.z * v2.z; acc.w += g0.wt.z * v2.w;
            acc.x += g0.wt.w * v3.x; acc.y += g0.wt.w * v3.y; acc.z += g0.wt.w * v3.z; acc.w += g0.wt.w * v3.w;
            acc.x += g1.wt.x * v4.x; acc.y += g1.wt.x * v4.y; acc.z += g1.wt.x * v4.z; acc.w += g1.wt.x * v4.w;
            acc.x += g1.wt.y * v5.x; acc.y += g1.wt.y * v5.y; acc.z += g1.wt.y * v5.z; acc.w += g1.wt.y * v5.w;
            acc.x += g1.wt.z * v6.x; acc.y += g1.wt.z * v6.y; acc.z += g1.wt.z * v6.z; acc.w += g1.wt.z * v6.w;
            acc.x += g1.wt.w * v7.x; acc.y += g1.wt.w * v7.y; acc.z += g1.wt.w * v7.z; acc.w += g1.wt.w * v7.w;
        }
        acc.x *= 0.25f; acc.y *= 0.25f; acc.z *= 0.25f; acc.w *= 0.25f;
        __stcs(o4 + (size_t)bin * 64, acc);   // streaming store: keep L2 for features
    }
}

extern "C" void kernel_launch(void* const* d_in, const int* in_sizes, int n_in,
                              void* d_out, int out_size) {
    // hw = 1024/stride: p2=256, p3=128, p4=64, p5=32, p6=16; C=256, B=2.
    const float *p2 = nullptr, *p3 = nullptr, *p4 = nullptr,
                *p5 = nullptr, *p6 = nullptr, *prop = nullptr;
    for (int i = 0; i < n_in; ++i) {
        switch (in_sizes[i]) {
            case 33554432:  p2   = (const float*)d_in[i]; break; // 2*256*256*256
            case 8388608:   p3   = (const float*)d_in[i]; break; // 2*128*128*256
            case 2097152:   p4   = (const float*)d_in[i]; break; // 2*64*64*256
            case 524288:    p5   = (const float*)d_in[i]; break; // 2*32*32*256
            case 131072:    p6   = (const float*)d_in[i]; break; // 2*16*16*256
            case 4096:      prop = (const float*)d_in[i]; break; // 2*512*4
        }
    }
    dim3 grid(RR, 2);
    roi_align_fpn_kernel<<<grid, 256>>>(p2, p3, p4, p5, p6, prop, (float*)d_out);
}